// round 7
// baseline (speedup 1.0000x reference)
#include <cuda_runtime.h>
#include <math.h>

#define EPS 1e-5f
typedef unsigned long long u64;

// Scratch (device globals — no runtime allocation)
__device__ float g_bufA[(size_t)64*192*56*56];     // 154 MB: conv1 out, region1 in-place
__device__ float g_bufB[(size_t)64*192*28*28];     // 38.5 MB: conv2 out, region2 in-place
__device__ float g_r1wT[(size_t)64*192*9*192];     // 85 MB: r1 weights [g][ci][k][co]
__device__ float g_r2wT[(size_t)16*192*9*192];     // 21 MB: r2 weights [g][ci][k][co]
__device__ float g_c2wT[(size_t)192*192*4];        // conv2 weights [ci][co][k]
__device__ float g_c3wT[(size_t)192*768*4];        // conv3 weights [ci][co][k]

__device__ __forceinline__ float gelu_exact(float x) {
    return 0.5f * x * (1.0f + erff(x * 0.70710678118654752f));
}

// ---- packed fp32x2 helpers (sm_103a FFMA2 path) ----
__device__ __forceinline__ u64 ffma2(u64 a, u64 b, u64 c) {
    u64 d; asm("fma.rn.f32x2 %0, %1, %2, %3;" : "=l"(d) : "l"(a), "l"(b), "l"(c)); return d;
}
__device__ __forceinline__ u64 dup2(float v) {
    u64 d; asm("mov.b64 %0, {%1, %1};" : "=l"(d) : "f"(v)); return d;
}
__device__ __forceinline__ void unpack2(u64 v, float& lo, float& hi) {
    asm("mov.b64 {%0, %1}, %2;" : "=f"(lo), "=f"(hi) : "l"(v));
}

// ---------------------------------------------------------------------------
// Weight transposes
// ---------------------------------------------------------------------------
__global__ void transpose_region_w(const float* __restrict__ w, float* __restrict__ wT, int total)
{
    int idx = blockIdx.x * blockDim.x + threadIdx.x;
    if (idx >= total) return;
    int co = idx % 192;
    int t  = idx / 192;
    int k  = t % 9;  t /= 9;
    int ci = t % 192;
    int g  = t / 192;
    wT[idx] = w[(((size_t)g*192 + co)*192 + ci)*9 + k];
}

__global__ void transpose_conv_w(const float* __restrict__ w, float* __restrict__ wT, int CO, int total)
{
    int idx = blockIdx.x * blockDim.x + threadIdx.x;
    if (idx >= total) return;
    int k  = idx & 3;
    int t  = idx >> 2;
    int co = t % CO;
    int ci = t / CO;
    wT[idx] = w[(((size_t)co*192) + ci)*4 + k];
}

// ---------------------------------------------------------------------------
// conv1
// ---------------------------------------------------------------------------
__global__ __launch_bounds__(192) void conv1_kernel(
    const float* __restrict__ x, const float* __restrict__ w,
    const float* __restrict__ bg, const float* __restrict__ bb,
    const float* __restrict__ bm, const float* __restrict__ bv)
{
    const int oh = blockIdx.x;
    const int b  = blockIdx.y;
    const int co = threadIdx.x;
    __shared__ float s_in[3*4*224];

    for (int i = co; i < 3*4*224; i += 192) {
        int ci = i / (4*224);
        int r  = (i / 224) & 3;
        int c  = i % 224;
        s_in[i] = x[(((size_t)b*3 + ci)*224 + (oh*4 + r))*224 + c];
    }
    float wreg[48];
    #pragma unroll
    for (int k = 0; k < 48; ++k) wreg[k] = w[co*48 + k];
    const float inv  = bg[co] * rsqrtf(bv[co] + EPS);
    const float beta = bb[co] - bm[co]*inv;
    __syncthreads();

    float* outp = &g_bufA[(((size_t)b*192 + co)*56 + oh)*56];
    for (int ow = 0; ow < 56; ++ow) {
        float acc = 0.f;
        #pragma unroll
        for (int ci = 0; ci < 3; ++ci)
            #pragma unroll
            for (int r = 0; r < 4; ++r)
                #pragma unroll
                for (int c = 0; c < 4; ++c)
                    acc = fmaf(wreg[(ci*4+r)*4+c], s_in[(ci*4+r)*224 + ow*4 + c], acc);
        outp[ow] = gelu_exact(acc*inv + beta);
    }
}

// ---------------------------------------------------------------------------
// region conv, packed-f32x2 + row-split. 192 threads: (pair 0..95, grp 0..1).
// grp0 -> output rows 0..3 (28 packed accs), grp1 -> rows 4..6 (21 accs).
// Weight LDG.64 prefetched one ci ahead (double-buffered registers).
// ---------------------------------------------------------------------------
template<int R0, int R1>
__device__ __forceinline__ void region_ci_compute(
    const u64* __restrict__ s_ci,    // &s[ci*56]
    const u64 w2[9], u64* acc)
{
    constexpr int IH0 = (R0 - 1 < 0) ? 0 : (R0 - 1);
    constexpr int IH1 = (R1 + 1 > 7) ? 7 : (R1 + 1);
    #pragma unroll
    for (int ih = IH0; ih < IH1; ++ih) {
        u64 in2[7];
        const u64* rowp = s_ci + ih*8;
        #pragma unroll
        for (int c = 0; c < 7; ++c) in2[c] = rowp[c];        // broadcast LDS.64
        #pragma unroll
        for (int ky = 0; ky < 3; ++ky) {
            const int oh = ih + 1 - ky;
            if (oh < R0 || oh >= R1) continue;               // compile-time pruned
            #pragma unroll
            for (int kx = 0; kx < 3; ++kx) {
                const u64 wk = w2[ky*3 + kx];
                #pragma unroll
                for (int ow = 0; ow < 7; ++ow) {
                    const int iw = ow + kx - 1;
                    if (iw < 0 || iw > 6) continue;
                    acc[(oh - R0)*7 + ow] = ffma2(wk, in2[iw], acc[(oh - R0)*7 + ow]);
                }
            }
        }
    }
}

template<int R0, int R1>
__device__ __forceinline__ void region_mainloop(
    const u64* __restrict__ wp,      // thread's weight base; index (ci*9+k)*96
    const u64* __restrict__ s, u64* acc)
{
    u64 wA[9], wB[9];
    #pragma unroll
    for (int k = 0; k < 9; ++k) wA[k] = wp[k*96];            // ci=0
    for (int ci = 0; ci < 192; ci += 2) {
        const u64* wpn = wp + (size_t)(ci + 1)*9*96;         // prefetch ci+1
        #pragma unroll
        for (int k = 0; k < 9; ++k) wB[k] = wpn[k*96];
        region_ci_compute<R0, R1>(&s[ci*56], wA, acc);
        const int cin = (ci + 2 <= 191) ? (ci + 2) : 191;    // prefetch ci+2 (clamped)
        const u64* wpn2 = wp + (size_t)cin*9*96;
        #pragma unroll
        for (int k = 0; k < 9; ++k) wA[k] = wpn2[k*96];
        region_ci_compute<R0, R1>(&s[(ci + 1)*56], wB, acc);
    }
}

template<int R0, int R1>
__device__ __forceinline__ void region_epilogue(
    const u64* __restrict__ s, u64* acc, float* __restrict__ dst,
    const float* __restrict__ bg, const float* __restrict__ bb,
    const float* __restrict__ bm, const float* __restrict__ bv,
    int g, int pair, int H, int base_h, int base_w)
{
    const int co0 = 2*pair, co1 = 2*pair + 1;
    const int gc0 = g*192 + co0, gc1 = g*192 + co1;
    const float inv0  = bg[gc0] * rsqrtf(bv[gc0] + EPS);
    const float beta0 = bb[gc0] - bm[gc0]*inv0;
    const float inv1  = bg[gc1] * rsqrtf(bv[gc1] + EPS);
    const float beta1 = bb[gc1] - bm[gc1]*inv1;

    #pragma unroll
    for (int j = 0; j < (R1 - R0)*7; ++j) {
        float a0, a1;
        unpack2(acc[j], a0, a1);
        const int row = R0 + j/7, c = j%7;
        float r0, r1, dummy;
        unpack2(s[co0*56 + row*8 + c], r0, dummy);
        unpack2(s[co1*56 + row*8 + c], r1, dummy);
        dst[((size_t)co0*H + base_h + row)*H + base_w + c] = gelu_exact(a0*inv0 + beta0) + r0;
        dst[((size_t)co1*H + base_h + row)*H + base_w + c] = gelu_exact(a1*inv1 + beta1) + r1;
    }
}

__global__ __launch_bounds__(192, 2) void region_kernel(
    const float* __restrict__ wT,
    const float* __restrict__ bg, const float* __restrict__ bb,
    const float* __restrict__ bm, const float* __restrict__ bv,
    int H)   // 56 (grid 8x8) or 28 (grid 4x4)
{
    extern __shared__ u64 s[];          // 192 planes * 56 u64 = 86016 B
    float* buf = (H == 56) ? g_bufA : g_bufB;
    const int GW = H / 7;
    const int b  = blockIdx.x;
    const int g  = blockIdx.y;
    const int t  = threadIdx.x;         // 0..191
    const int pair = (t < 96) ? t : (t - 96);
    const int base_h = (g / GW) * 7;
    const int base_w = (g % GW) * 7;

    const float* src = buf + (size_t)b*192*H*H;
    for (int i = t; i < 192*49; i += 192) {
        int ci = i / 49, p = i % 49;
        float v = src[((size_t)ci*H + base_h + p/7)*H + base_w + p%7];
        s[ci*56 + (p/7)*8 + (p%7)] = dup2(v);
    }
    __syncthreads();

    const u64* wp = reinterpret_cast<const u64*>(wT + (size_t)g*192*9*192) + pair;
    float* dst = buf + (size_t)b*192*H*H;

    if (t < 96) {
        u64 acc[28];
        #pragma unroll
        for (int j = 0; j < 28; ++j) acc[j] = 0ull;
        region_mainloop<0, 4>(wp, s, acc);
        region_epilogue<0, 4>(s, acc, dst, bg, bb, bm, bv, g, pair, H, base_h, base_w);
    } else {
        u64 acc[21];
        #pragma unroll
        for (int j = 0; j < 21; ++j) acc[j] = 0ull;
        region_mainloop<4, 7>(wp, s, acc);
        region_epilogue<4, 7>(s, acc, dst, bg, bb, bm, bv, g, pair, H, base_h, base_w);
    }
}

// ---------------------------------------------------------------------------
// conv2
// ---------------------------------------------------------------------------
__global__ __launch_bounds__(192) void conv2_kernel(
    const float* __restrict__ wT,
    const float* __restrict__ bg, const float* __restrict__ bb,
    const float* __restrict__ bm, const float* __restrict__ bv)
{
    const int q  = blockIdx.x;   // 0..1
    const int oh = blockIdx.y;   // 0..27
    const int b  = blockIdx.z;   // 0..63
    const int co = threadIdx.x;  // 0..191
    __shared__ float s_in[192*2*28];

    for (int i = co; i < 192*2*28; i += 192) {
        int ci = i / 56, r = (i/28) & 1, c = i % 28;
        s_in[i] = g_bufA[(((size_t)b*192 + ci)*56 + 2*oh + r)*56 + q*28 + c];
    }
    __syncthreads();

    float acc[14];
    #pragma unroll
    for (int j = 0; j < 14; ++j) acc[j] = 0.f;

    const float4* w4 = reinterpret_cast<const float4*>(wT) + co;
    for (int ci = 0; ci < 192; ++ci) {
        const float4 wv = w4[ci*192];
        const float4* r0 = reinterpret_cast<const float4*>(&s_in[ci*56]);
        const float4* r1 = reinterpret_cast<const float4*>(&s_in[ci*56 + 28]);
        #pragma unroll
        for (int p = 0; p < 7; ++p) {
            float4 a = r0[p], c = r1[p];
            acc[2*p]   = fmaf(wv.x, a.x, fmaf(wv.y, a.y, fmaf(wv.z, c.x, fmaf(wv.w, c.y, acc[2*p]))));
            acc[2*p+1] = fmaf(wv.x, a.z, fmaf(wv.y, a.w, fmaf(wv.z, c.z, fmaf(wv.w, c.w, acc[2*p+1]))));
        }
    }
    const float inv  = bg[co] * rsqrtf(bv[co] + EPS);
    const float beta = bb[co] - bm[co]*inv;
    float* op = &g_bufB[(((size_t)b*192 + co)*28 + oh)*28 + q*14];
    #pragma unroll
    for (int ow = 0; ow < 14; ++ow) op[ow] = gelu_exact(acc[ow]*inv + beta);
}

// ---------------------------------------------------------------------------
// conv3
// ---------------------------------------------------------------------------
__global__ __launch_bounds__(768) void conv3_kernel(
    const float* __restrict__ wT,
    const float* __restrict__ bg, const float* __restrict__ bb,
    const float* __restrict__ bm, const float* __restrict__ bv,
    float* __restrict__ out)
{
    const int oh = blockIdx.x;   // 0..13
    const int b  = blockIdx.y;   // 0..63
    const int co = threadIdx.x;  // 0..767
    __shared__ float s_in[192*2*28];

    for (int i = co; i < 192*2*28; i += 768) {
        int ci = i / 56, r = (i/28) & 1, c = i % 28;
        s_in[i] = g_bufB[(((size_t)b*192 + ci)*28 + 2*oh + r)*28 + c];
    }
    __syncthreads();

    float acc[14];
    #pragma unroll
    for (int j = 0; j < 14; ++j) acc[j] = 0.f;

    const float4* w4 = reinterpret_cast<const float4*>(wT) + co;
    for (int ci = 0; ci < 192; ++ci) {
        const float4 wv = w4[ci*768];
        const float4* r0 = reinterpret_cast<const float4*>(&s_in[ci*56]);
        const float4* r1 = reinterpret_cast<const float4*>(&s_in[ci*56 + 28]);
        #pragma unroll
        for (int p = 0; p < 7; ++p) {
            float4 a = r0[p], c = r1[p];
            acc[2*p]   = fmaf(wv.x, a.x, fmaf(wv.y, a.y, fmaf(wv.z, c.x, fmaf(wv.w, c.y, acc[2*p]))));
            acc[2*p+1] = fmaf(wv.x, a.z, fmaf(wv.y, a.w, fmaf(wv.z, c.z, fmaf(wv.w, c.w, acc[2*p+1]))));
        }
    }
    const float inv  = bg[co] * rsqrtf(bv[co] + EPS);
    const float beta = bb[co] - bm[co]*inv;
    #pragma unroll
    for (int ow = 0; ow < 14; ++ow)
        out[((size_t)b*196 + oh*14 + ow)*768 + co] = acc[ow]*inv + beta;
}

// ---------------------------------------------------------------------------
extern "C" void kernel_launch(void* const* d_in, const int* in_sizes, int n_in,
                              void* d_out, int out_size)
{
    const float* x       = (const float*)d_in[0];
    const float* c1w     = (const float*)d_in[1];
    const float* b1g = (const float*)d_in[2],  *b1b = (const float*)d_in[3];
    const float* b1m = (const float*)d_in[4],  *b1v = (const float*)d_in[5];
    const float* r1w     = (const float*)d_in[6];
    const float* r1g = (const float*)d_in[7],  *r1b = (const float*)d_in[8];
    const float* r1m = (const float*)d_in[9],  *r1v = (const float*)d_in[10];
    const float* c2w     = (const float*)d_in[11];
    const float* b2g = (const float*)d_in[12], *b2b = (const float*)d_in[13];
    const float* b2m = (const float*)d_in[14], *b2v = (const float*)d_in[15];
    const float* r2w     = (const float*)d_in[16];
    const float* r2g = (const float*)d_in[17], *r2b = (const float*)d_in[18];
    const float* r2m = (const float*)d_in[19], *r2v = (const float*)d_in[20];
    const float* c3w     = (const float*)d_in[21];
    const float* b3g = (const float*)d_in[22], *b3b = (const float*)d_in[23];
    const float* b3m = (const float*)d_in[24], *b3v = (const float*)d_in[25];
    float* out = (float*)d_out;

    float *r1wT, *r2wT, *c2wT, *c3wT;
    cudaGetSymbolAddress((void**)&r1wT, g_r1wT);
    cudaGetSymbolAddress((void**)&r2wT, g_r2wT);
    cudaGetSymbolAddress((void**)&c2wT, g_c2wT);
    cudaGetSymbolAddress((void**)&c3wT, g_c3wT);

    {   // weight transposes
        int t1 = 64*192*192*9;
        transpose_region_w<<<(t1 + 255)/256, 256>>>(r1w, r1wT, t1);
        int t2 = 16*192*192*9;
        transpose_region_w<<<(t2 + 255)/256, 256>>>(r2w, r2wT, t2);
        int t3 = 192*192*4;
        transpose_conv_w<<<(t3 + 255)/256, 256>>>(c2w, c2wT, 192, t3);
        int t4 = 192*768*4;
        transpose_conv_w<<<(t4 + 255)/256, 256>>>(c3w, c3wT, 768, t4);
    }

    const int region_smem = 192*56*sizeof(u64);   // 86016 B
    cudaFuncSetAttribute(region_kernel, cudaFuncAttributeMaxDynamicSharedMemorySize, region_smem);

    conv1_kernel<<<dim3(56, 64), 192>>>(x, c1w, b1g, b1b, b1m, b1v);
    region_kernel<<<dim3(64, 64), 192, region_smem>>>(r1wT, r1g, r1b, r1m, r1v, 56);
    conv2_kernel<<<dim3(2, 28, 64), 192>>>(c2wT, b2g, b2b, b2m, b2v);
    region_kernel<<<dim3(64, 16), 192, region_smem>>>(r2wT, r2g, r2b, r2m, r2v, 28);
    conv3_kernel<<<dim3(14, 64), 768>>>(c3wT, b3g, b3b, b3m, b3v, out);
}

// round 8
// speedup vs baseline: 1.0009x; 1.0009x over previous
#include <cuda_runtime.h>
#include <math.h>

#define EPS 1e-5f
typedef unsigned long long u64;

// Scratch (device globals — no runtime allocation)
__device__ float g_bufA[(size_t)64*192*56*56];     // 154 MB: conv1 out, region1 in-place
__device__ float g_bufB[(size_t)64*192*28*28];     // 38.5 MB: conv2 out, region2 in-place
__device__ float g_r1wT[(size_t)64*192*9*192];     // 85 MB: r1 weights [g][ci][k][co]
__device__ float g_r2wT[(size_t)16*192*9*192];     // 21 MB: r2 weights [g][ci][k][co]
__device__ float g_c2wT[(size_t)192*192*4];        // conv2 weights [ci][co][k]
__device__ float g_c3wT[(size_t)192*768*4];        // conv3 weights [ci][co][k]

__device__ __forceinline__ float gelu_exact(float x) {
    return 0.5f * x * (1.0f + erff(x * 0.70710678118654752f));
}

// ---- packed fp32x2 helpers (sm_103a FFMA2 path) ----
__device__ __forceinline__ u64 ffma2(u64 a, u64 b, u64 c) {
    u64 d; asm("fma.rn.f32x2 %0, %1, %2, %3;" : "=l"(d) : "l"(a), "l"(b), "l"(c)); return d;
}
__device__ __forceinline__ u64 dup2(float v) {
    u64 d; asm("mov.b64 %0, {%1, %1};" : "=l"(d) : "f"(v)); return d;
}
__device__ __forceinline__ void unpack2(u64 v, float& lo, float& hi) {
    asm("mov.b64 {%0, %1}, %2;" : "=f"(lo), "=f"(hi) : "l"(v));
}

// ---------------------------------------------------------------------------
// Weight transposes
// ---------------------------------------------------------------------------
__global__ void transpose_region_w(const float* __restrict__ w, float* __restrict__ wT, int total)
{
    int idx = blockIdx.x * blockDim.x + threadIdx.x;
    if (idx >= total) return;
    int co = idx % 192;
    int t  = idx / 192;
    int k  = t % 9;  t /= 9;
    int ci = t % 192;
    int g  = t / 192;
    wT[idx] = w[(((size_t)g*192 + co)*192 + ci)*9 + k];
}

__global__ void transpose_conv_w(const float* __restrict__ w, float* __restrict__ wT, int CO, int total)
{
    int idx = blockIdx.x * blockDim.x + threadIdx.x;
    if (idx >= total) return;
    int k  = idx & 3;
    int t  = idx >> 2;
    int co = t % CO;
    int ci = t / CO;
    wT[idx] = w[(((size_t)co*192) + ci)*4 + k];
}

// ---------------------------------------------------------------------------
// conv1
// ---------------------------------------------------------------------------
__global__ __launch_bounds__(192) void conv1_kernel(
    const float* __restrict__ x, const float* __restrict__ w,
    const float* __restrict__ bg, const float* __restrict__ bb,
    const float* __restrict__ bm, const float* __restrict__ bv)
{
    const int oh = blockIdx.x;
    const int b  = blockIdx.y;
    const int co = threadIdx.x;
    __shared__ float s_in[3*4*224];

    for (int i = co; i < 3*4*224; i += 192) {
        int ci = i / (4*224);
        int r  = (i / 224) & 3;
        int c  = i % 224;
        s_in[i] = x[(((size_t)b*3 + ci)*224 + (oh*4 + r))*224 + c];
    }
    float wreg[48];
    #pragma unroll
    for (int k = 0; k < 48; ++k) wreg[k] = w[co*48 + k];
    const float inv  = bg[co] * rsqrtf(bv[co] + EPS);
    const float beta = bb[co] - bm[co]*inv;
    __syncthreads();

    float* outp = &g_bufA[(((size_t)b*192 + co)*56 + oh)*56];
    for (int ow = 0; ow < 56; ++ow) {
        float acc = 0.f;
        #pragma unroll
        for (int ci = 0; ci < 3; ++ci)
            #pragma unroll
            for (int r = 0; r < 4; ++r)
                #pragma unroll
                for (int c = 0; c < 4; ++c)
                    acc = fmaf(wreg[(ci*4+r)*4+c], s_in[(ci*4+r)*224 + ow*4 + c], acc);
        outp[ow] = gelu_exact(acc*inv + beta);
    }
}

// ---------------------------------------------------------------------------
// region conv, packed-f32x2 + row-split. 192 threads: (pair 0..95, grp 0..1).
// grp0 -> output rows 0..3 (28 packed accs), grp1 -> rows 4..6 (21 accs).
// Weight LDG.64 prefetched one ci ahead (double-buffered registers).
// ---------------------------------------------------------------------------
template<int R0, int R1>
__device__ __forceinline__ void region_ci_compute(
    const u64* __restrict__ s_ci,    // &s[ci*56]
    const u64 w2[9], u64* acc)
{
    constexpr int IH0 = (R0 - 1 < 0) ? 0 : (R0 - 1);
    constexpr int IH1 = (R1 + 1 > 7) ? 7 : (R1 + 1);
    #pragma unroll
    for (int ih = IH0; ih < IH1; ++ih) {
        u64 in2[7];
        const u64* rowp = s_ci + ih*8;
        #pragma unroll
        for (int c = 0; c < 7; ++c) in2[c] = rowp[c];        // broadcast LDS.64
        #pragma unroll
        for (int ky = 0; ky < 3; ++ky) {
            const int oh = ih + 1 - ky;
            if (oh < R0 || oh >= R1) continue;               // compile-time pruned
            #pragma unroll
            for (int kx = 0; kx < 3; ++kx) {
                const u64 wk = w2[ky*3 + kx];
                #pragma unroll
                for (int ow = 0; ow < 7; ++ow) {
                    const int iw = ow + kx - 1;
                    if (iw < 0 || iw > 6) continue;
                    acc[(oh - R0)*7 + ow] = ffma2(wk, in2[iw], acc[(oh - R0)*7 + ow]);
                }
            }
        }
    }
}

template<int R0, int R1>
__device__ __forceinline__ void region_mainloop(
    const u64* __restrict__ wp,      // thread's weight base; index (ci*9+k)*96
    const u64* __restrict__ s, u64* acc)
{
    u64 wA[9], wB[9];
    #pragma unroll
    for (int k = 0; k < 9; ++k) wA[k] = wp[k*96];            // ci=0
    for (int ci = 0; ci < 192; ci += 2) {
        const u64* wpn = wp + (size_t)(ci + 1)*9*96;         // prefetch ci+1
        #pragma unroll
        for (int k = 0; k < 9; ++k) wB[k] = wpn[k*96];
        region_ci_compute<R0, R1>(&s[ci*56], wA, acc);
        const int cin = (ci + 2 <= 191) ? (ci + 2) : 191;    // prefetch ci+2 (clamped)
        const u64* wpn2 = wp + (size_t)cin*9*96;
        #pragma unroll
        for (int k = 0; k < 9; ++k) wA[k] = wpn2[k*96];
        region_ci_compute<R0, R1>(&s[(ci + 1)*56], wB, acc);
    }
}

template<int R0, int R1>
__device__ __forceinline__ void region_epilogue(
    const u64* __restrict__ s, u64* acc, float* __restrict__ dst,
    const float* __restrict__ bg, const float* __restrict__ bb,
    const float* __restrict__ bm, const float* __restrict__ bv,
    int g, int pair, int H, int base_h, int base_w)
{
    const int co0 = 2*pair, co1 = 2*pair + 1;
    const int gc0 = g*192 + co0, gc1 = g*192 + co1;
    const float inv0  = bg[gc0] * rsqrtf(bv[gc0] + EPS);
    const float beta0 = bb[gc0] - bm[gc0]*inv0;
    const float inv1  = bg[gc1] * rsqrtf(bv[gc1] + EPS);
    const float beta1 = bb[gc1] - bm[gc1]*inv1;

    #pragma unroll
    for (int j = 0; j < (R1 - R0)*7; ++j) {
        float a0, a1;
        unpack2(acc[j], a0, a1);
        const int row = R0 + j/7, c = j%7;
        float r0, r1, dummy;
        unpack2(s[co0*56 + row*8 + c], r0, dummy);
        unpack2(s[co1*56 + row*8 + c], r1, dummy);
        dst[((size_t)co0*H + base_h + row)*H + base_w + c] = gelu_exact(a0*inv0 + beta0) + r0;
        dst[((size_t)co1*H + base_h + row)*H + base_w + c] = gelu_exact(a1*inv1 + beta1) + r1;
    }
}

__global__ __launch_bounds__(192, 2) void region_kernel(
    const float* __restrict__ wT,
    const float* __restrict__ bg, const float* __restrict__ bb,
    const float* __restrict__ bm, const float* __restrict__ bv,
    int H)   // 56 (grid 8x8) or 28 (grid 4x4)
{
    extern __shared__ u64 s[];          // 192 planes * 56 u64 = 86016 B
    float* buf = (H == 56) ? g_bufA : g_bufB;
    const int GW = H / 7;
    const int b  = blockIdx.x;
    const int g  = blockIdx.y;
    const int t  = threadIdx.x;         // 0..191
    const int pair = (t < 96) ? t : (t - 96);
    const int base_h = (g / GW) * 7;
    const int base_w = (g % GW) * 7;

    const float* src = buf + (size_t)b*192*H*H;
    for (int i = t; i < 192*49; i += 192) {
        int ci = i / 49, p = i % 49;
        float v = src[((size_t)ci*H + base_h + p/7)*H + base_w + p%7];
        s[ci*56 + (p/7)*8 + (p%7)] = dup2(v);
    }
    __syncthreads();

    const u64* wp = reinterpret_cast<const u64*>(wT + (size_t)g*192*9*192) + pair;
    float* dst = buf + (size_t)b*192*H*H;

    if (t < 96) {
        u64 acc[28];
        #pragma unroll
        for (int j = 0; j < 28; ++j) acc[j] = 0ull;
        region_mainloop<0, 4>(wp, s, acc);
        region_epilogue<0, 4>(s, acc, dst, bg, bb, bm, bv, g, pair, H, base_h, base_w);
    } else {
        u64 acc[21];
        #pragma unroll
        for (int j = 0; j < 21; ++j) acc[j] = 0ull;
        region_mainloop<4, 7>(wp, s, acc);
        region_epilogue<4, 7>(s, acc, dst, bg, bb, bm, bv, g, pair, H, base_h, base_w);
    }
}

// ---------------------------------------------------------------------------
// conv2
// ---------------------------------------------------------------------------
__global__ __launch_bounds__(192) void conv2_kernel(
    const float* __restrict__ wT,
    const float* __restrict__ bg, const float* __restrict__ bb,
    const float* __restrict__ bm, const float* __restrict__ bv)
{
    const int q  = blockIdx.x;   // 0..1
    const int oh = blockIdx.y;   // 0..27
    const int b  = blockIdx.z;   // 0..63
    const int co = threadIdx.x;  // 0..191
    __shared__ float s_in[192*2*28];

    for (int i = co; i < 192*2*28; i += 192) {
        int ci = i / 56, r = (i/28) & 1, c = i % 28;
        s_in[i] = g_bufA[(((size_t)b*192 + ci)*56 + 2*oh + r)*56 + q*28 + c];
    }
    __syncthreads();

    float acc[14];
    #pragma unroll
    for (int j = 0; j < 14; ++j) acc[j] = 0.f;

    const float4* w4 = reinterpret_cast<const float4*>(wT) + co;
    for (int ci = 0; ci < 192; ++ci) {
        const float4 wv = w4[ci*192];
        const float4* r0 = reinterpret_cast<const float4*>(&s_in[ci*56]);
        const float4* r1 = reinterpret_cast<const float4*>(&s_in[ci*56 + 28]);
        #pragma unroll
        for (int p = 0; p < 7; ++p) {
            float4 a = r0[p], c = r1[p];
            acc[2*p]   = fmaf(wv.x, a.x, fmaf(wv.y, a.y, fmaf(wv.z, c.x, fmaf(wv.w, c.y, acc[2*p]))));
            acc[2*p+1] = fmaf(wv.x, a.z, fmaf(wv.y, a.w, fmaf(wv.z, c.z, fmaf(wv.w, c.w, acc[2*p+1]))));
        }
    }
    const float inv  = bg[co] * rsqrtf(bv[co] + EPS);
    const float beta = bb[co] - bm[co]*inv;
    float* op = &g_bufB[(((size_t)b*192 + co)*28 + oh)*28 + q*14];
    #pragma unroll
    for (int ow = 0; ow < 14; ++ow) op[ow] = gelu_exact(acc[ow]*inv + beta);
}

// ---------------------------------------------------------------------------
// conv3
// ---------------------------------------------------------------------------
__global__ __launch_bounds__(768) void conv3_kernel(
    const float* __restrict__ wT,
    const float* __restrict__ bg, const float* __restrict__ bb,
    const float* __restrict__ bm, const float* __restrict__ bv,
    float* __restrict__ out)
{
    const int oh = blockIdx.x;   // 0..13
    const int b  = blockIdx.y;   // 0..63
    const int co = threadIdx.x;  // 0..767
    __shared__ float s_in[192*2*28];

    for (int i = co; i < 192*2*28; i += 768) {
        int ci = i / 56, r = (i/28) & 1, c = i % 28;
        s_in[i] = g_bufB[(((size_t)b*192 + ci)*28 + 2*oh + r)*28 + c];
    }
    __syncthreads();

    float acc[14];
    #pragma unroll
    for (int j = 0; j < 14; ++j) acc[j] = 0.f;

    const float4* w4 = reinterpret_cast<const float4*>(wT) + co;
    for (int ci = 0; ci < 192; ++ci) {
        const float4 wv = w4[ci*768];
        const float4* r0 = reinterpret_cast<const float4*>(&s_in[ci*56]);
        const float4* r1 = reinterpret_cast<const float4*>(&s_in[ci*56 + 28]);
        #pragma unroll
        for (int p = 0; p < 7; ++p) {
            float4 a = r0[p], c = r1[p];
            acc[2*p]   = fmaf(wv.x, a.x, fmaf(wv.y, a.y, fmaf(wv.z, c.x, fmaf(wv.w, c.y, acc[2*p]))));
            acc[2*p+1] = fmaf(wv.x, a.z, fmaf(wv.y, a.w, fmaf(wv.z, c.z, fmaf(wv.w, c.w, acc[2*p+1]))));
        }
    }
    const float inv  = bg[co] * rsqrtf(bv[co] + EPS);
    const float beta = bb[co] - bm[co]*inv;
    #pragma unroll
    for (int ow = 0; ow < 14; ++ow)
        out[((size_t)b*196 + oh*14 + ow)*768 + co] = acc[ow]*inv + beta;
}

// ---------------------------------------------------------------------------
extern "C" void kernel_launch(void* const* d_in, const int* in_sizes, int n_in,
                              void* d_out, int out_size)
{
    const float* x       = (const float*)d_in[0];
    const float* c1w     = (const float*)d_in[1];
    const float* b1g = (const float*)d_in[2],  *b1b = (const float*)d_in[3];
    const float* b1m = (const float*)d_in[4],  *b1v = (const float*)d_in[5];
    const float* r1w     = (const float*)d_in[6];
    const float* r1g = (const float*)d_in[7],  *r1b = (const float*)d_in[8];
    const float* r1m = (const float*)d_in[9],  *r1v = (const float*)d_in[10];
    const float* c2w     = (const float*)d_in[11];
    const float* b2g = (const float*)d_in[12], *b2b = (const float*)d_in[13];
    const float* b2m = (const float*)d_in[14], *b2v = (const float*)d_in[15];
    const float* r2w     = (const float*)d_in[16];
    const float* r2g = (const float*)d_in[17], *r2b = (const float*)d_in[18];
    const float* r2m = (const float*)d_in[19], *r2v = (const float*)d_in[20];
    const float* c3w     = (const float*)d_in[21];
    const float* b3g = (const float*)d_in[22], *b3b = (const float*)d_in[23];
    const float* b3m = (const float*)d_in[24], *b3v = (const float*)d_in[25];
    float* out = (float*)d_out;

    float *r1wT, *r2wT, *c2wT, *c3wT;
    cudaGetSymbolAddress((void**)&r1wT, g_r1wT);
    cudaGetSymbolAddress((void**)&r2wT, g_r2wT);
    cudaGetSymbolAddress((void**)&c2wT, g_c2wT);
    cudaGetSymbolAddress((void**)&c3wT, g_c3wT);

    {   // weight transposes
        int t1 = 64*192*192*9;
        transpose_region_w<<<(t1 + 255)/256, 256>>>(r1w, r1wT, t1);
        int t2 = 16*192*192*9;
        transpose_region_w<<<(t2 + 255)/256, 256>>>(r2w, r2wT, t2);
        int t3 = 192*192*4;
        transpose_conv_w<<<(t3 + 255)/256, 256>>>(c2w, c2wT, 192, t3);
        int t4 = 192*768*4;
        transpose_conv_w<<<(t4 + 255)/256, 256>>>(c3w, c3wT, 768, t4);
    }

    const int region_smem = 192*56*sizeof(u64);   // 86016 B
    cudaFuncSetAttribute(region_kernel, cudaFuncAttributeMaxDynamicSharedMemorySize, region_smem);

    conv1_kernel<<<dim3(56, 64), 192>>>(x, c1w, b1g, b1b, b1m, b1v);
    region_kernel<<<dim3(64, 64), 192, region_smem>>>(r1wT, r1g, r1b, r1m, r1v, 56);
    conv2_kernel<<<dim3(2, 28, 64), 192>>>(c2wT, b2g, b2b, b2m, b2v);
    region_kernel<<<dim3(64, 16), 192, region_smem>>>(r2wT, r2g, r2b, r2m, r2v, 28);
    conv3_kernel<<<dim3(14, 64), 768>>>(c3wT, b3g, b3b, b3m, b3v, out);
}